// round 15
// baseline (speedup 1.0000x reference)
#include <cuda_runtime.h>
#include <cuda_fp16.h>
#include <cstdint>

#define BB   2
#define TT   2048
#define HH   16
#define DH   64
#define DD   1024
#define BH   (BB*HH)
#define TILE 128
#define NT   (TT/TILE)
#define NPAIRS (NT*(NT+1)/2)

__device__ __forceinline__ uint32_t smem_u32(const void* p) {
    uint32_t a;
    asm("{ .reg .u64 t; cvta.to.shared.u64 t, %1; cvt.u32.u64 %0, t; }"
        : "=r"(a) : "l"(p));
    return a;
}

#define LDSM4(r, addr) \
    asm volatile("ldmatrix.sync.aligned.m8n8.x4.shared.b16 {%0,%1,%2,%3}, [%4];" \
        : "=r"((r)[0]), "=r"((r)[1]), "=r"((r)[2]), "=r"((r)[3]) : "r"(addr))

#define MMA16816(d, a, b0, b1) \
    asm volatile("mma.sync.aligned.m16n8k16.row.col.f32.f16.f16.f32 " \
        "{%0,%1,%2,%3},{%4,%5,%6,%7},{%8,%9},{%0,%1,%2,%3};" \
        : "+f"((d)[0]), "+f"((d)[1]), "+f"((d)[2]), "+f"((d)[3]) \
        : "r"((a)[0]), "r"((a)[1]), "r"((a)[2]), "r"((a)[3]), "r"(b0), "r"(b1))

#define LDBH 144   // bytes per smem fp16 tile row (64 halfs + 16B pad)

// ============================================================================
// Fused wedge: per CTA (pair i<=j, head bh):
//   x -> normalize -> V images; S = A - A^T (hi/lo fp16) in smem;
//   Svh = fp16(Vh @ S) via mma (in-place over the V-hi image);
//   W tile = Svh @ [Vh|Vl]^T (2-pass fp16 mma); staged coalesced epilogue
//   + skew-mirror tile. grid (NPAIRS, BH), 256 threads, 2 CTA/SM.
// ============================================================================
#define P_SH   0                     // S^T hi (64xLDBH)            9216
#define P_SL   9216                  // S^T lo                      9216
#define P_A    18432                 // V-hi tile i -> Svh tile     18432
#define P_Bh   36864                 // B hi tile j (aliases A-stage f32 16640)
#define P_Bl   55296                 // B lo tile j                 18432
#define P_STG  73728                 // per-warp epilogue stage     38912
#define WSLICE 4864
#define SMEM_F (P_STG + 8*WSLICE)    // 112640

__global__ __launch_bounds__(256, 2) void wedge_fused(const float* __restrict__ x,
                                                      const float* __restrict__ A,
                                                      float* __restrict__ out) {
    extern __shared__ char sm[];
    const uint32_t sb = smem_u32(sm);
    float* As = (float*)(sm + P_Bh);          // A-stage aliases B-hi region
    const int tid  = threadIdx.x;
    const int w    = tid >> 5;
    const int lane = tid & 31;
    const int bh   = blockIdx.y;
    const int b    = bh / HH;
    const int h    = bh % HH;
    const int wm   = w >> 2;
    const int wn   = w & 3;

    int p = blockIdx.x;
    int i = 0;
    while (p >= NT - i) { p -= NT - i; ++i; }
    const int j  = i + p;
    const int i0 = i * TILE;
    const int j0 = j * TILE;

    // ---- (1) issue x loads for both tiles: 16 rows each, MLP 32 ----
    float2 vi[16], vj[16];
    {
        const float2* xi = (const float2*)(x + ((size_t)(b * TT + i0 + w * 16)) * DD + h * DH) + lane;
        const float2* xj = (const float2*)(x + ((size_t)(b * TT + j0 + w * 16)) * DD + h * DH) + lane;
        #pragma unroll
        for (int r = 0; r < 16; ++r) vi[r] = xi[(size_t)r * (DD / 2)];
        #pragma unroll
        for (int r = 0; r < 16; ++r) vj[r] = xj[(size_t)r * (DD / 2)];
    }

    // ---- (2) stage A coalesced into (aliased) f32 buffer ----
    {
        const float4* Ah4 = (const float4*)(A + (size_t)h * DH * DH);
        #pragma unroll
        for (int q = 0; q < 4; ++q) {
            const int f  = q * 256 + tid;
            const int d  = f >> 4;
            const int c4 = (f & 15) * 4;
            const float4 a = Ah4[f];
            As[d * 65 + c4 + 0] = a.x;
            As[d * 65 + c4 + 1] = a.y;
            As[d * 65 + c4 + 2] = a.z;
            As[d * 65 + c4 + 3] = a.w;
        }
    }
    __syncthreads();

    // ---- (3) S images + normalize tile i -> V-hi image at P_A ----
    #pragma unroll
    for (int q = 0; q < 16; ++q) {
        const int idx = q * 256 + tid;
        const int e = idx >> 6, d = idx & 63;
        const float s = As[d * 65 + e] - As[e * 65 + d];
        const __half hi = __float2half_rn(s);
        *(__half*)(sm + P_SH + e * LDBH + d * 2) = hi;
        *(__half*)(sm + P_SL + e * LDBH + d * 2) = __float2half_rn(s - __half2float(hi));
    }
    #pragma unroll
    for (int r = 0; r < 16; ++r) {
        float ss = vi[r].x * vi[r].x + vi[r].y * vi[r].y;
        #pragma unroll
        for (int o = 16; o; o >>= 1) ss += __shfl_xor_sync(0xffffffffu, ss, o);
        const float sc = 1.0f / fmaxf(sqrtf(ss), 1e-12f);
        const __half hx = __float2half_rn(vi[r].x * sc);
        const __half hy = __float2half_rn(vi[r].y * sc);
        *(__half2*)(sm + P_A + (w * 16 + r) * LDBH + lane * 4) = __half2(hx, hy);
    }
    __syncthreads();   // A-stage reads done -> B region writable

    // ---- (4) normalize tile j -> B hi/lo images ----
    #pragma unroll
    for (int r = 0; r < 16; ++r) {
        float ss = vj[r].x * vj[r].x + vj[r].y * vj[r].y;
        #pragma unroll
        for (int o = 16; o; o >>= 1) ss += __shfl_xor_sync(0xffffffffu, ss, o);
        const float sc = 1.0f / fmaxf(sqrtf(ss), 1e-12f);
        vj[r].x *= sc; vj[r].y *= sc;
        const __half hx = __float2half_rn(vj[r].x);
        const __half hy = __float2half_rn(vj[r].y);
        const __half2 H(hx, hy);
        const __half2 L = __floats2half2_rn(vj[r].x - __half2float(hx),
                                            vj[r].y - __half2float(hy));
        *(__half2*)(sm + P_Bh + (w * 16 + r) * LDBH + lane * 4) = H;
        *(__half2*)(sm + P_Bl + (w * 16 + r) * LDBH + lane * 4) = L;
    }
    __syncthreads();

    // ---- (5) Svh = fp16(Vh_i @ S), in-place over P_A (warp-private rows) ----
    {
        const uint32_t aB = sb + P_A + (uint32_t)(w * 16 + (lane & 15)) * LDBH
                          + ((uint32_t)(lane >> 4)) * 16;
        const uint32_t bB = sb + P_SH + (uint32_t)((lane & 7) | ((lane >> 1) & 8)) * LDBH
                          + ((uint32_t)(lane & 8)) * 2;
        float acc[8][4];
        #pragma unroll
        for (int q = 0; q < 8; ++q)
            #pragma unroll
            for (int c = 0; c < 4; ++c) acc[q][c] = 0.f;
        #pragma unroll
        for (int kk = 0; kk < 4; ++kk) {
            uint32_t ah[4];
            LDSM4(ah, aB + kk * 32);
            #pragma unroll
            for (int n16 = 0; n16 < 4; ++n16) {
                uint32_t bhf[4], blf[4];
                LDSM4(bhf, bB + n16 * 16 * LDBH + kk * 32);
                LDSM4(blf, bB + (P_SL - P_SH) + n16 * 16 * LDBH + kk * 32);
                MMA16816(acc[2 * n16],     ah, bhf[0], bhf[1]);
                MMA16816(acc[2 * n16 + 1], ah, bhf[2], bhf[3]);
                MMA16816(acc[2 * n16],     ah, blf[0], blf[1]);
                MMA16816(acc[2 * n16 + 1], ah, blf[2], blf[3]);
            }
        }
        const int r = w * 16 + (lane >> 2);
        #pragma unroll
        for (int q = 0; q < 8; ++q) {
            const int col = q * 8 + (lane & 3) * 2;
            *(__half2*)(sm + P_A + r * LDBH + col * 2)       = __floats2half2_rn(acc[q][0], acc[q][1]);
            *(__half2*)(sm + P_A + (r + 8) * LDBH + col * 2) = __floats2half2_rn(acc[q][2], acc[q][3]);
        }
    }
    __syncthreads();

    // ---- (6) mainloop: W = Svh @ [Bh|Bl]^T, 2x4 warp tiling ----
    const uint32_t aB = sb + P_A + (uint32_t)(wm * 64 + (lane & 15)) * LDBH
                      + ((uint32_t)(lane >> 4)) * 16;
    const uint32_t bn = (uint32_t)((lane & 7) | ((lane >> 1) & 8));
    const uint32_t bB = sb + P_Bh + ((uint32_t)(wn * 32) + bn) * LDBH
                      + ((uint32_t)(lane & 8)) * 2;

    float acc[4][4][4];
    #pragma unroll
    for (int mt = 0; mt < 4; ++mt)
        #pragma unroll
        for (int nt = 0; nt < 4; ++nt)
            #pragma unroll
            for (int q = 0; q < 4; ++q) acc[mt][nt][q] = 0.f;

    #pragma unroll
    for (int kk = 0; kk < 4; ++kk) {
        uint32_t bh0[4], bh1[4], bl0[4], bl1[4];
        LDSM4(bh0, bB + kk * 32);
        LDSM4(bh1, bB + 16 * LDBH + kk * 32);
        LDSM4(bl0, bB + (P_Bl - P_Bh) + kk * 32);
        LDSM4(bl1, bB + (P_Bl - P_Bh) + 16 * LDBH + kk * 32);
        #pragma unroll
        for (int mt = 0; mt < 4; ++mt) {
            uint32_t ah[4];
            LDSM4(ah, aB + mt * 16 * LDBH + kk * 32);
            MMA16816(acc[mt][0], ah, bh0[0], bh0[1]);
            MMA16816(acc[mt][1], ah, bh0[2], bh0[3]);
            MMA16816(acc[mt][2], ah, bh1[0], bh1[1]);
            MMA16816(acc[mt][3], ah, bh1[2], bh1[3]);
            MMA16816(acc[mt][0], ah, bl0[0], bl0[1]);
            MMA16816(acc[mt][1], ah, bl0[2], bl0[3]);
            MMA16816(acc[mt][2], ah, bl1[0], bl1[1]);
            MMA16816(acc[mt][3], ah, bl1[2], bl1[3]);
        }
    }

    // ---- (7) per-warp staged epilogue (proven form) ----
    float* outb = out + (size_t)bh * TT * TT;
    float* stg = (float*)(sm + P_STG + w * WSLICE);
    const int rql = lane >> 2;
    const int cql = (lane & 3) * 2;

    #pragma unroll
    for (int mt = 0; mt < 4; ++mt) {
        #pragma unroll
        for (int nt = 0; nt < 4; ++nt) {
            const int col = nt * 8 + cql;
            *(float2*)&stg[rql * 40 + col]       = make_float2(acc[mt][nt][0], acc[mt][nt][1]);
            *(float2*)&stg[(rql + 8) * 40 + col] = make_float2(acc[mt][nt][2], acc[mt][nt][3]);
        }
        __syncwarp();
        #pragma unroll
        for (int pp = 0; pp < 4; ++pp) {
            const int r = pp * 4 + (lane >> 3);
            const float4 vv = *(const float4*)&stg[r * 40 + (lane & 7) * 4];
            const int grow = i0 + wm * 64 + mt * 16 + r;
            __stcs((float4*)&outb[(size_t)grow * TT + j0 + wn * 32 + (lane & 7) * 4], vv);
        }
        __syncwarp();
    }

    if (i != j) {
        #pragma unroll
        for (int cc = 0; cc < 2; ++cc) {
            #pragma unroll
            for (int ntl = 0; ntl < 2; ++ntl) {
                const int nt = cc * 2 + ntl;
                const int c0 = ntl * 8 + cql;
                #pragma unroll
                for (int mt = 0; mt < 4; ++mt) {
                    const int rbase = mt * 16 + rql;
                    stg[c0 * 76 + rbase]           = -acc[mt][nt][0];
                    stg[(c0 + 1) * 76 + rbase]     = -acc[mt][nt][1];
                    stg[c0 * 76 + rbase + 8]       = -acc[mt][nt][2];
                    stg[(c0 + 1) * 76 + rbase + 8] = -acc[mt][nt][3];
                }
            }
            __syncwarp();
            #pragma unroll
            for (int pp = 0; pp < 8; ++pp) {
                const int c = pp * 2 + (lane >> 4);
                const float4 vv = *(const float4*)&stg[c * 76 + (lane & 15) * 4];
                const int grow = j0 + wn * 32 + cc * 16 + c;
                __stcs((float4*)&outb[(size_t)grow * TT + i0 + wm * 64 + (lane & 15) * 4], vv);
            }
            __syncwarp();
        }
    }
}

// ============================================================================
extern "C" void kernel_launch(void* const* d_in, const int* in_sizes, int n_in,
                              void* d_out, int out_size) {
    (void)in_sizes; (void)n_in; (void)out_size;
    const float* x = (const float*)d_in[0];
    const float* A = (const float*)d_in[1];
    float* out = (float*)d_out;

    cudaFuncSetAttribute(wedge_fused, cudaFuncAttributeMaxDynamicSharedMemorySize, SMEM_F);
    wedge_fused<<<dim3(NPAIRS, BH), 256, SMEM_F>>>(x, A, out);
}

// round 16
// speedup vs baseline: 1.8714x; 1.8714x over previous
#include <cuda_runtime.h>
#include <cuda_fp16.h>
#include <cstdint>

#define BB   2
#define TT   2048
#define HH   16
#define DH   64
#define DD   1024
#define BH   (BB*HH)
#define TILE 128
#define NT   (TT/TILE)
#define NPAIRS (NT*(NT+1)/2)

// fp16 scratch (8 MB each, 24 MB total -> L2 resident)
__device__ __half g_Vh [(size_t)BH * TT * DH];
__device__ __half g_Vl [(size_t)BH * TT * DH];
__device__ __half g_Svh[(size_t)BH * TT * DH];

__device__ __forceinline__ uint32_t smem_u32(const void* p) {
    uint32_t a;
    asm("{ .reg .u64 t; cvta.to.shared.u64 t, %1; cvt.u32.u64 %0, t; }"
        : "=r"(a) : "l"(p));
    return a;
}

#define LDSM4(r, addr) \
    asm volatile("ldmatrix.sync.aligned.m8n8.x4.shared.b16 {%0,%1,%2,%3}, [%4];" \
        : "=r"((r)[0]), "=r"((r)[1]), "=r"((r)[2]), "=r"((r)[3]) : "r"(addr))

#define MMA16816(d, a, b0, b1) \
    asm volatile("mma.sync.aligned.m16n8k16.row.col.f32.f16.f16.f32 " \
        "{%0,%1,%2,%3},{%4,%5,%6,%7},{%8,%9},{%0,%1,%2,%3};" \
        : "+f"((d)[0]), "+f"((d)[1]), "+f"((d)[2]), "+f"((d)[3]) \
        : "r"((a)[0]), "r"((a)[1]), "r"((a)[2]), "r"((a)[3]), "r"(b0), "r"(b1))

#define CP_ASYNC16(dst, src) \
    asm volatile("cp.async.cg.shared.global [%0], [%1], 16;" \
        :: "r"(dst), "l"(src) : "memory")
#define CP_COMMIT() asm volatile("cp.async.commit_group;" ::: "memory")
#define CP_WAIT0()  asm volatile("cp.async.wait_group 0;" ::: "memory")

#define LDBH 144   // bytes per smem fp16 tile row (64 halfs + 16B pad)

// ============================================================================
// Kernel 1 (round-12 form; grid swapped to bh-fastest): normalize rows ->
// Vh/Vl, Sv = V*S via mma.sync, Svh = fp16(Sv). grid (BH, NT*2), 128 thr.
// ============================================================================
#define Q_BSH 0                  // S^T hi (64x64 fp16, LDBH)   9216 B
#define Q_BSL 9216               // S^T lo                       9216 B
#define Q_VH  18432              // V hi (64x64, LDBH)           9216 B
#define Q_VL  27648              // V lo                         9216 B
#define Q_AS  36864              // A staged, 64x65 f32         16640 B
#define SMEM_PREP 53504

__global__ __launch_bounds__(128) void prep_kernel(const float* __restrict__ x,
                                                   const float* __restrict__ A) {
    extern __shared__ char sp[];
    const uint32_t sb = smem_u32(sp);
    float* As = (float*)(sp + Q_AS);
    const int tid  = threadIdx.x;
    const int warp = tid >> 5;
    const int lane = tid & 31;
    const int bh = blockIdx.x;           // bh fastest -> dense x coverage
    const int b  = bh / HH;
    const int h  = bh % HH;
    const int t0c = blockIdx.y * 64;

    // (1) issue ALL 16 x-row loads for this warp (MLP 16)
    float2 v[16];
    {
        const float* xbase = x + ((size_t)(b * TT + t0c + warp * 16)) * DD + h * DH + 2 * lane;
        #pragma unroll
        for (int r = 0; r < 16; ++r)
            v[r] = *(const float2*)(xbase + (size_t)r * DD);
    }

    // (2) stage A coalesced (independent work; hides x-load latency)
    {
        const float4* Ah4 = (const float4*)(A + (size_t)h * DH * DH);
        #pragma unroll
        for (int p = 0; p < 8; ++p) {
            const int f  = p * 128 + tid;
            const int d  = f >> 4;
            const int c4 = (f & 15) * 4;
            const float4 a = Ah4[f];
            As[d * 65 + c4 + 0] = a.x;
            As[d * 65 + c4 + 1] = a.y;
            As[d * 65 + c4 + 2] = a.z;
            As[d * 65 + c4 + 3] = a.w;
        }
    }
    __syncthreads();

    // (3) Bs[e][d] = A[d][e] - A[e][d], split hi/lo fp16
    #pragma unroll
    for (int p = 0; p < 32; ++p) {
        const int idx = p * 128 + tid;
        const int e = idx >> 6, d = idx & 63;
        const float s = As[d * 65 + e] - As[e * 65 + d];
        const __half hi = __float2half_rn(s);
        const __half lo = __float2half_rn(s - __half2float(hi));
        *(__half*)(sp + Q_BSH + e * LDBH + d * 2) = hi;
        *(__half*)(sp + Q_BSL + e * LDBH + d * 2) = lo;
    }

    // (4) normalize + split + write V images
    #pragma unroll
    for (int r = 0; r < 16; ++r) {
        float ss = v[r].x * v[r].x + v[r].y * v[r].y;
        #pragma unroll
        for (int o = 16; o; o >>= 1) ss += __shfl_xor_sync(0xffffffffu, ss, o);
        const float sc = 1.0f / fmaxf(sqrtf(ss), 1e-12f);
        v[r].x *= sc; v[r].y *= sc;
        const __half hx = __float2half_rn(v[r].x);
        const __half hy = __float2half_rn(v[r].y);
        const __half2 H(hx, hy);
        const __half2 L = __floats2half2_rn(v[r].x - __half2float(hx),
                                            v[r].y - __half2float(hy));
        const int lr   = warp * 16 + r;
        const size_t gofs = ((size_t)bh * TT + t0c + lr) * DH + 2 * lane;
        *(__half2*)&g_Vh[gofs] = H;
        *(__half2*)&g_Vl[gofs] = L;
        *(__half2*)(sp + Q_VH + lr * LDBH + lane * 4) = H;
        *(__half2*)(sp + Q_VL + lr * LDBH + lane * 4) = L;
    }
    __syncthreads();

    // (5) Sv = V @ S via mma (2 passes: Vh*Sh + Vh*Sl), warp = m16
    const uint32_t aB = sb + Q_VH + (uint32_t)(warp * 16 + (lane & 15)) * LDBH
                      + ((uint32_t)(lane >> 4)) * 16;
    const uint32_t bB = sb + Q_BSH + (uint32_t)((lane & 7) | ((lane >> 1) & 8)) * LDBH
                      + ((uint32_t)(lane & 8)) * 2;

    float acc[8][4];
    #pragma unroll
    for (int q = 0; q < 8; ++q)
        #pragma unroll
        for (int c = 0; c < 4; ++c) acc[q][c] = 0.f;

    #pragma unroll
    for (int kk = 0; kk < 4; ++kk) {
        uint32_t ah[4];
        LDSM4(ah, aB + kk * 32);
        #pragma unroll
        for (int n16 = 0; n16 < 4; ++n16) {
            uint32_t bhf[4], blf[4];
            LDSM4(bhf, bB + n16 * 16 * LDBH + kk * 32);
            LDSM4(blf, bB + (Q_BSL - Q_BSH) + n16 * 16 * LDBH + kk * 32);
            MMA16816(acc[2 * n16],     ah, bhf[0], bhf[1]);
            MMA16816(acc[2 * n16 + 1], ah, bhf[2], bhf[3]);
            MMA16816(acc[2 * n16],     ah, blf[0], blf[1]);
            MMA16816(acc[2 * n16 + 1], ah, blf[2], blf[3]);
        }
    }

    const int r = warp * 16 + (lane >> 2);
    #pragma unroll
    for (int q = 0; q < 8; ++q) {
        const int col = q * 8 + (lane & 3) * 2;
        const __half2 h0 = __floats2half2_rn(acc[q][0], acc[q][1]);
        const __half2 h1 = __floats2half2_rn(acc[q][2], acc[q][3]);
        *(__half2*)&g_Svh[((size_t)bh * TT + t0c + r) * DH + col]     = h0;
        *(__half2*)&g_Svh[((size_t)bh * TT + t0c + r + 8) * DH + col] = h1;
    }
}

// ============================================================================
// Kernel 2: fp16 mma wedge (proven round-10/12 form, UNCHANGED): 2-pass,
// cp.async tile loads, per-warp staged coalesced epilogue.
// grid (NPAIRS, BH), 256 thr, 2 CTA/SM.
// ============================================================================
#define T_AH   0
#define T_BH   18432
#define T_BL   36864
#define P_STG  55296
#define WSLICE 4864
#define SMEM_WEDGE (P_STG + 8*WSLICE)    // 94208

__device__ __forceinline__ void copy_tile_async(uint32_t dst, const __half* __restrict__ src,
                                                int tid) {
    #pragma unroll
    for (int p = 0; p < 4; ++p) {
        const int f   = p * 256 + tid;
        const int row = f >> 3;
        const int c   = f & 7;
        CP_ASYNC16(dst + row * LDBH + c * 16, (const char*)src + f * 16);
    }
}

__global__ __launch_bounds__(256, 2) void wedge_mma(float* __restrict__ out) {
    extern __shared__ char sm[];
    const uint32_t sb = smem_u32(sm);
    const int tid  = threadIdx.x;
    const int w    = tid >> 5;
    const int lane = tid & 31;
    const int bh   = blockIdx.y;
    const int wm   = w >> 2;
    const int wn   = w & 3;

    int p = blockIdx.x;
    int i = 0;
    while (p >= NT - i) { p -= NT - i; ++i; }
    const int j  = i + p;
    const int i0 = i * TILE;
    const int j0 = j * TILE;

    float* outb = out + (size_t)bh * TT * TT;

    copy_tile_async(sb + T_AH, g_Svh + ((size_t)bh * TT + i0) * DH, tid);
    copy_tile_async(sb + T_BH, g_Vh  + ((size_t)bh * TT + j0) * DH, tid);
    copy_tile_async(sb + T_BL, g_Vl  + ((size_t)bh * TT + j0) * DH, tid);
    CP_COMMIT();
    CP_WAIT0();
    __syncthreads();

    const uint32_t aB = sb + T_AH + (uint32_t)(wm * 64 + (lane & 15)) * LDBH
                      + ((uint32_t)(lane >> 4)) * 16;
    const uint32_t bn = (uint32_t)((lane & 7) | ((lane >> 1) & 8));
    const uint32_t bB = sb + T_BH + ((uint32_t)(wn * 32) + bn) * LDBH
                      + ((uint32_t)(lane & 8)) * 2;

    float acc[4][4][4];
    #pragma unroll
    for (int mt = 0; mt < 4; ++mt)
        #pragma unroll
        for (int nt = 0; nt < 4; ++nt)
            #pragma unroll
            for (int q = 0; q < 4; ++q) acc[mt][nt][q] = 0.f;

    #pragma unroll
    for (int kk = 0; kk < 4; ++kk) {
        uint32_t bh0[4], bh1[4], bl0[4], bl1[4];
        LDSM4(bh0, bB + kk * 32);
        LDSM4(bh1, bB + 16 * LDBH + kk * 32);
        LDSM4(bl0, bB + (T_BL - T_BH) + kk * 32);
        LDSM4(bl1, bB + (T_BL - T_BH) + 16 * LDBH + kk * 32);
        #pragma unroll
        for (int mt = 0; mt < 4; ++mt) {
            uint32_t ah[4];
            LDSM4(ah, aB + mt * 16 * LDBH + kk * 32);
            MMA16816(acc[mt][0], ah, bh0[0], bh0[1]);
            MMA16816(acc[mt][1], ah, bh0[2], bh0[3]);
            MMA16816(acc[mt][2], ah, bh1[0], bh1[1]);
            MMA16816(acc[mt][3], ah, bh1[2], bh1[3]);
            MMA16816(acc[mt][0], ah, bl0[0], bl0[1]);
            MMA16816(acc[mt][1], ah, bl0[2], bl0[3]);
            MMA16816(acc[mt][2], ah, bl1[0], bl1[1]);
            MMA16816(acc[mt][3], ah, bl1[2], bl1[3]);
        }
    }

    // ---- per-warp epilogue (no CTA barriers) ----
    float* stg = (float*)(sm + P_STG + w * WSLICE);
    const int rql = lane >> 2;
    const int cql = (lane & 3) * 2;

    // normal tile (i,j)
    #pragma unroll
    for (int mt = 0; mt < 4; ++mt) {
        #pragma unroll
        for (int nt = 0; nt < 4; ++nt) {
            const int col = nt * 8 + cql;
            *(float2*)&stg[rql * 40 + col]       = make_float2(acc[mt][nt][0], acc[mt][nt][1]);
            *(float2*)&stg[(rql + 8) * 40 + col] = make_float2(acc[mt][nt][2], acc[mt][nt][3]);
        }
        __syncwarp();
        #pragma unroll
        for (int pp = 0; pp < 4; ++pp) {
            const int r = pp * 4 + (lane >> 3);
            const float4 vv = *(const float4*)&stg[r * 40 + (lane & 7) * 4];
            const int grow = i0 + wm * 64 + mt * 16 + r;
            __stcs((float4*)&outb[(size_t)grow * TT + j0 + wn * 32 + (lane & 7) * 4], vv);
        }
        __syncwarp();
    }

    // mirror tile (j,i) = -transpose, staged (stride 76, conflict-free)
    if (i != j) {
        #pragma unroll
        for (int cc = 0; cc < 2; ++cc) {
            #pragma unroll
            for (int ntl = 0; ntl < 2; ++ntl) {
                const int nt = cc * 2 + ntl;
                const int c0 = ntl * 8 + cql;
                #pragma unroll
                for (int mt = 0; mt < 4; ++mt) {
                    const int rbase = mt * 16 + rql;
                    stg[c0 * 76 + rbase]           = -acc[mt][nt][0];
                    stg[(c0 + 1) * 76 + rbase]     = -acc[mt][nt][1];
                    stg[c0 * 76 + rbase + 8]       = -acc[mt][nt][2];
                    stg[(c0 + 1) * 76 + rbase + 8] = -acc[mt][nt][3];
                }
            }
            __syncwarp();
            #pragma unroll
            for (int pp = 0; pp < 8; ++pp) {
                const int c = pp * 2 + (lane >> 4);
                const float4 vv = *(const float4*)&stg[c * 76 + (lane & 15) * 4];
                const int grow = j0 + wn * 32 + cc * 16 + c;
                __stcs((float4*)&outb[(size_t)grow * TT + i0 + wm * 64 + (lane & 15) * 4], vv);
            }
            __syncwarp();
        }
    }
}

// ============================================================================
extern "C" void kernel_launch(void* const* d_in, const int* in_sizes, int n_in,
                              void* d_out, int out_size) {
    (void)in_sizes; (void)n_in; (void)out_size;
    const float* x = (const float*)d_in[0];
    const float* A = (const float*)d_in[1];
    float* out = (float*)d_out;

    cudaFuncSetAttribute(prep_kernel, cudaFuncAttributeMaxDynamicSharedMemorySize, SMEM_PREP);
    prep_kernel<<<dim3(BH, NT * 2), 128, SMEM_PREP>>>(x, A);

    cudaFuncSetAttribute(wedge_mma, cudaFuncAttributeMaxDynamicSharedMemorySize, SMEM_WEDGE);
    wedge_mma<<<dim3(NPAIRS, BH), 256, SMEM_WEDGE>>>(out);
}